// round 9
// baseline (speedup 1.0000x reference)
#include <cuda_runtime.h>
#include <cstdint>

// ---------------------------------------------------------------------------
// Fully fused: one kernel. Blocks take monotonic tickets; the 32 first-
// scheduled blocks of each launch (epoch) compute the weight collapse
//   p1 = Wl3.wl4 ; q = Wl2.p1 + wl4 ; M = Wl1.q + wl4
//   c0 = bl1.q + bl2.p1 + bl3.wl4 + bl4
//   v_n = W2 @ M_n ; t_n = W1 @ v_n ; s_n = b1.v_n ; c1 = c0 + sum_n b2.M_n
// into g_TSC while every other block stages its x/edge tile from DRAM.
// Then per sample: out = sum_{n,p} (Agg^2)[n,p](x_p.t_n) + sum_n R[n] s_n + c1
// All inter-block sync uses monotonic counters (replay-safe, reset-free).
// ---------------------------------------------------------------------------

__device__ float g_p1[256];
__device__ float g_q[256];
__device__ float g_M[256];
__device__ float g_TSC[61];   // T[56], s[4], c1
__device__ int   g_ticket;    // block tickets (monotonic)
__device__ int   g_sbar;      // performer stage barrier (monotonic, +96/epoch)
__device__ int   g_done;      // finalize completions (monotonic, +1/epoch)

__device__ __forceinline__ void l2_prefetch(const void* p) {
    asm volatile("prefetch.global.L2 [%0];" :: "l"(p));
}
__device__ __forceinline__ unsigned long long pack2(float lo, float hi) {
    unsigned long long r;
    asm("mov.b64 %0, {%1, %2};" : "=l"(r) : "f"(lo), "f"(hi));
    return r;
}
__device__ __forceinline__ void fma2(unsigned long long& d,
                                     unsigned long long a, unsigned long long b) {
    asm("fma.rn.f32x2 %0, %1, %2, %0;" : "+l"(d) : "l"(a), "l"(b));
}
__device__ __forceinline__ float unpack_sum(unsigned long long v) {
    float lo, hi;
    asm("mov.b64 {%0, %1}, %2;" : "=f"(lo), "=f"(hi) : "l"(v));
    return lo + hi;
}
__device__ __forceinline__ float warp_sum(float a) {
    #pragma unroll
    for (int o = 16; o > 0; o >>= 1) a += __shfl_xor_sync(0xFFFFFFFFu, a, o);
    return a;
}

// performer-only barrier (32 blocks), epoch-offset monotonic tickets
__device__ __forceinline__ void pbar(int epoch, int stage) {
    __syncthreads();
    if (threadIdx.x == 0) {
        __threadfence();
        atomicAdd(&g_sbar, 1);
        int target = epoch * 96 + (stage + 1) * 32;
        while ((*(volatile int*)&g_sbar) - target < 0) __nanosleep(40);
        __threadfence();
    }
    __syncthreads();
}

#define TPB 128

__global__ __launch_bounds__(TPB, 5)
void gcn_fused(const float* __restrict__ x, const int* __restrict__ eidx,
               float* __restrict__ out, int nblk,
               const float* __restrict__ W1, const float* __restrict__ b1,
               const float* __restrict__ W2, const float* __restrict__ b2,
               const float* __restrict__ Wl1, const float* __restrict__ bl1,
               const float* __restrict__ Wl2, const float* __restrict__ bl2,
               const float* __restrict__ Wl3, const float* __restrict__ bl3,
               const float* __restrict__ wl4, const float* __restrict__ bl4)
{
    __shared__ float4 sx4[TPB * 15];   // 60 floats/sample (pad 56->60)
    __shared__ int4   se4[TPB * 7];    // 28 ints/sample  (pad 24->28)
    __shared__ float  sT[64];
    __shared__ int    s_id, s_epoch;
    int tid = threadIdx.x, wid = tid >> 5, lane = tid & 31;

    if (tid == 0) {
        int t = atomicAdd(&g_ticket, 1);
        s_id = t % nblk;
        s_epoch = t / nblk;
    }
    __syncthreads();
    int id = s_id, epoch = s_epoch;

    // ================= performer path: ids 0..31 compute the weight collapse
    if (id < 32) {
        // prefetch later-stage weights into L2 (overlaps stage-0 cold reads)
        int g = id * TPB + tid;                          // 0..4095
        if (g < 2048) l2_prefetch(Wl2 + (size_t)g * 32);
        else          l2_prefetch(Wl1 + (size_t)(g - 2048) * 32);
        if (id == 0) {
            l2_prefetch(W2 + (size_t)tid * 64);          // 256 lines
            l2_prefetch(W2 + (size_t)(tid + 128) * 64);
            if (tid < 56) l2_prefetch(W1 + (size_t)tid * 32);
        }

        int r = id * 8 + wid * 2;   // 2 rows per warp, 8 rows per block
        {   // stage 0: p1 = Wl3 . wl4
            const float* r0 = Wl3 + (size_t)r * 256;
            float a0 = 0.f, a1 = 0.f;
            #pragma unroll
            for (int k = 0; k < 8; k++) {
                float v = wl4[lane + 32 * k];
                a0 += r0[lane + 32 * k] * v;
                a1 += r0[256 + lane + 32 * k] * v;
            }
            a0 = warp_sum(a0); a1 = warp_sum(a1);
            if (lane == 0) { g_p1[r] = a0; g_p1[r + 1] = a1; }
        }
        pbar(epoch, 0);
        {   // stage 1: q = Wl2 . p1 + wl4
            const float* r0 = Wl2 + (size_t)r * 256;
            float a0 = 0.f, a1 = 0.f;
            #pragma unroll
            for (int k = 0; k < 8; k++) {
                float v = g_p1[lane + 32 * k];
                a0 += r0[lane + 32 * k] * v;
                a1 += r0[256 + lane + 32 * k] * v;
            }
            a0 = warp_sum(a0); a1 = warp_sum(a1);
            if (lane == 0) { g_q[r] = a0 + wl4[r]; g_q[r + 1] = a1 + wl4[r + 1]; }
        }
        pbar(epoch, 1);
        {   // stage 2: M = Wl1 . q + wl4
            const float* r0 = Wl1 + (size_t)r * 256;
            float a0 = 0.f, a1 = 0.f;
            #pragma unroll
            for (int k = 0; k < 8; k++) {
                float v = g_q[lane + 32 * k];
                a0 += r0[lane + 32 * k] * v;
                a1 += r0[256 + lane + 32 * k] * v;
            }
            a0 = warp_sum(a0); a1 = warp_sum(a1);
            if (lane == 0) { g_M[r] = a0 + wl4[r]; g_M[r + 1] = a1 + wl4[r + 1]; }
        }
        pbar(epoch, 2);

        if (id == 0) {
            // finalize with 128 threads; scratch unioned into sx4 (disjoint life)
            float* sM   = (float*)sx4;        // 256
            float* sV   = sM + 256;           // 512
            float* sRed = sV + 512;           // 4
            sM[tid]       = g_M[tid];
            sM[tid + 128] = g_M[tid + 128];
            float contrib = bl1[tid] * g_q[tid] + bl2[tid] * g_p1[tid]
                          + bl3[tid] * wl4[tid]
                          + bl1[tid+128] * g_q[tid+128] + bl2[tid+128] * g_p1[tid+128]
                          + bl3[tid+128] * wl4[tid+128];
            __syncthreads();
            if (tid < 64)
                contrib += b2[tid] * (sM[tid] + sM[64+tid] + sM[128+tid] + sM[192+tid]);
            contrib = warp_sum(contrib);
            if (lane == 0) sRed[wid] = contrib;
            // V[n*128+k] = W2[k,:] . M_n  (4 outputs/thread)
            #pragma unroll
            for (int rep = 0; rep < 4; rep++) {
                int o = tid + rep * 128;
                int n = o >> 7, k = o & 127;
                const float4* w4 = (const float4*)(W2 + (size_t)k * 64);
                const float4* m4 = (const float4*)(sM + n * 64);
                float a = 0.f;
                #pragma unroll
                for (int j = 0; j < 16; j++) {
                    float4 w = w4[j], mm = m4[j];
                    a += w.x * mm.x + w.y * mm.y + w.z * mm.z + w.w * mm.w;
                }
                sV[o] = a;
            }
            __syncthreads();
            // T/s/c1: warp wid handles rows wid*16 .. wid*16+15
            for (int j = 0; j < 16; j++) {
                int rr = wid * 16 + j;
                if (rr < 60) {
                    int nn = (rr < 56) ? (rr / 14) : (rr - 56);
                    float4 w = (rr < 56)
                        ? ((const float4*)(W1 + (size_t)(rr % 14) * 128))[lane]
                        : ((const float4*)b1)[lane];
                    float4 vv = ((const float4*)(sV + nn * 128))[lane];
                    float a = w.x*vv.x + w.y*vv.y + w.z*vv.z + w.w*vv.w;
                    a = warp_sum(a);
                    if (lane == 0) g_TSC[rr] = a;
                } else if (rr == 60 && lane == 0) {
                    g_TSC[60] = bl4[0] + sRed[0] + sRed[1] + sRed[2] + sRed[3];
                }
            }
            __syncthreads();
            if (tid == 0) { __threadfence(); atomicAdd(&g_done, 1); }
        }
    }

    // ================= all blocks: stage tile (overlaps precompute) =========
    const float4* Xg = (const float4*)x + (size_t)blockIdx.x * TPB * 14;
    const int4*   Eg = (const int4*)eidx + (size_t)blockIdx.x * TPB * 6;
    float4 xv[14];
    int4   ev[6];
    #pragma unroll
    for (int i = 0; i < 14; i++) xv[i] = Xg[i * TPB + tid];
    #pragma unroll
    for (int i = 0; i < 6; i++)  ev[i] = Eg[i * TPB + tid];
    #pragma unroll
    for (int i = 0; i < 14; i++) {
        int idx4 = i * TPB + tid;
        int s = idx4 / 14, j = idx4 % 14;
        sx4[s * 15 + j] = xv[i];
    }
    #pragma unroll
    for (int i = 0; i < 6; i++) {
        int i4 = i * TPB + tid;
        int s = i4 / 6, rr = i4 % 6;
        se4[s * 7 + rr] = ev[i];
    }
    __syncthreads();

    // ---- per-sample graph math (no TSC needed yet)
    const int4* me4 = se4 + tid * 7;
    int4 f0 = me4[0], f1 = me4[1], f2 = me4[2];
    int4 f3 = me4[3], f4 = me4[4], f5 = me4[5];
    int es[12] = {f0.x,f0.y,f0.z,f0.w, f1.x,f1.y,f1.z,f1.w, f2.x,f2.y,f2.z,f2.w};
    int ed[12] = {f3.x,f3.y,f3.z,f3.w, f4.x,f4.y,f4.z,f4.w, f5.x,f5.y,f5.z,f5.w};
    unsigned h0 = 1u + (1u << 20);         // self loops: codes 0, 5
    unsigned h1 = (1u << 8) + (1u << 28);  // codes 10, 15
    #pragma unroll
    for (int e = 0; e < 12; e++) {
        int code = (ed[e] << 2) | es[e];
        unsigned inc = 1u << ((code & 7) << 2);
        if (code & 8) h1 += inc; else h0 += inc;
    }
    float c[16];
    #pragma unroll
    for (int qd = 0; qd < 8; qd++) {
        c[qd]     = (float)((h0 >> (qd * 4)) & 15u);
        c[qd + 8] = (float)((h1 >> (qd * 4)) & 15u);
    }
    float dinv[4];
    #pragma unroll
    for (int dd = 0; dd < 4; dd++)
        dinv[dd] = rsqrtf(c[4*dd] + c[4*dd+1] + c[4*dd+2] + c[4*dd+3]);
    float A[16];
    #pragma unroll
    for (int dd = 0; dd < 4; dd++)
        #pragma unroll
        for (int ss = 0; ss < 4; ss++)
            A[dd*4+ss] = c[dd*4+ss] * dinv[dd] * dinv[ss];
    float A2[16], R[4];
    #pragma unroll
    for (int n = 0; n < 4; n++) {
        R[n] = A[n*4] + A[n*4+1] + A[n*4+2] + A[n*4+3];
        #pragma unroll
        for (int p = 0; p < 4; p++) {
            A2[n*4+p] = A[n*4+0] * A[0*4+p] + A[n*4+1] * A[1*4+p]
                      + A[n*4+2] * A[2*4+p] + A[n*4+3] * A[3*4+p];
        }
    }

    // ---- wait for TSC (usually already done: staging hid the precompute)
    if (tid == 0) {
        while ((*(volatile int*)&g_done) - (epoch + 1) < 0) __nanosleep(100);
        __threadfence();
    }
    __syncthreads();
    if (tid < 61) sT[tid] = __ldcg(g_TSC + tid);
    __syncthreads();

    // ---- d2[p*4+n] = x_p . t_n, packed f32x2 FMA, x read straight from smem
    const float* mxf = (const float*)(sx4 + tid * 15);
    unsigned long long d2[16];
    #pragma unroll
    for (int i = 0; i < 16; i++) d2[i] = 0ULL;
    #pragma unroll
    for (int q = 0; q < 7; q++) {
        unsigned long long xp[4], tp[4];
        #pragma unroll
        for (int p = 0; p < 4; p++)
            xp[p] = *(const unsigned long long*)(mxf + p * 14 + 2 * q);  // LDS.64
        #pragma unroll
        for (int n = 0; n < 4; n++)
            tp[n] = *(const unsigned long long*)(sT + n * 14 + 2 * q);
        #pragma unroll
        for (int p = 0; p < 4; p++)
            #pragma unroll
            for (int n = 0; n < 4; n++)
                fma2(d2[p*4+n], xp[p], tp[n]);
    }

    float acc = sT[60] + R[0]*sT[56] + R[1]*sT[57] + R[2]*sT[58] + R[3]*sT[59];
    #pragma unroll
    for (int n = 0; n < 4; n++)
        #pragma unroll
        for (int p = 0; p < 4; p++)
            acc += A2[n*4+p] * unpack_sum(d2[p*4+n]);

    out[blockIdx.x * TPB + tid] = acc;
}

extern "C" void kernel_launch(void* const* d_in, const int* in_sizes, int n_in,
                              void* d_out, int out_size)
{
    const float* x   = (const float*)d_in[0];
    const int*   ei  = (const int*)  d_in[1];
    const float* W1  = (const float*)d_in[2];
    const float* b1  = (const float*)d_in[3];
    const float* W2  = (const float*)d_in[4];
    const float* b2  = (const float*)d_in[5];
    const float* Wl1 = (const float*)d_in[6];
    const float* bl1 = (const float*)d_in[7];
    const float* Wl2 = (const float*)d_in[8];
    const float* bl2 = (const float*)d_in[9];
    const float* Wl3 = (const float*)d_in[10];
    const float* bl3 = (const float*)d_in[11];
    const float* wl4 = (const float*)d_in[12];
    const float* bl4 = (const float*)d_in[13];

    int B = in_sizes[0] / 56;   // 262144
    int nblk = B / TPB;         // 2048

    gcn_fused<<<nblk, TPB>>>(x, ei, (float*)d_out, nblk,
                             W1, b1, W2, b2, Wl1, bl1, Wl2, bl2,
                             Wl3, bl3, wl4, bl4);
}

// round 11
// speedup vs baseline: 1.0088x; 1.0088x over previous
#include <cuda_runtime.h>
#include <cstdint>

// ---------------------------------------------------------------------------
// out[b] = sum_{n,p} (Agg_b^2)[n,p] * (x_b[p] . t_n)
//        + sum_n rowsum(Agg_b)[n] * s_n  +  c1
// Precompute (ONE block, all stages + finalize, shared-resident):
//   p1 = Wl3.wl4 ; q = Wl2.p1 + wl4 ; M = Wl1.q + wl4
//   c0 = bl1.q + bl2.p1 + bl3.wl4 + bl4
//   v_n = W2 @ M_n ; t_n = W1 @ v_n ; s_n = b1.v_n ; c1 = c0 + sum_n b2.M_n
// ---------------------------------------------------------------------------

__device__ float g_TSC[61];   // T[56], s[4], c1

__device__ __forceinline__ void l2_prefetch(const void* p) {
    asm volatile("prefetch.global.L2 [%0];" :: "l"(p));
}
__device__ __forceinline__ void fma2(unsigned long long& d,
                                     unsigned long long a, unsigned long long b) {
    asm("fma.rn.f32x2 %0, %1, %2, %0;" : "+l"(d) : "l"(a), "l"(b));
}
__device__ __forceinline__ float unpack_sum(unsigned long long v) {
    float lo, hi;
    asm("mov.b64 {%0, %1}, %2;" : "=f"(lo), "=f"(hi) : "l"(v));
    return lo + hi;
}
__device__ __forceinline__ float warp_sum(float a) {
    #pragma unroll
    for (int o = 16; o > 0; o >>= 1) a += __shfl_xor_sync(0xFFFFFFFFu, a, o);
    return a;
}

// one 256x256 matvec stage: sout[r] = W[r,:].sv (+ sadd[r]); 8 warps, 4-row ILP
__device__ __forceinline__ void mv_stage(const float* __restrict__ W,
                                         const float* sv, const float* sadd,
                                         float* sout, int wid, int lane)
{
    const float4* W4 = (const float4*)W;
    const float4* v4 = (const float4*)sv;
    float4 vb0 = v4[lane], vb1 = v4[32 + lane];
    #pragma unroll
    for (int b = 0; b < 8; b++) {
        int r = wid * 32 + b * 4;
        float s[4];
        #pragma unroll
        for (int j = 0; j < 4; j++) {
            float4 a0 = W4[(size_t)(r + j) * 64 + lane];
            float4 a1 = W4[(size_t)(r + j) * 64 + 32 + lane];
            s[j] = a0.x*vb0.x + a0.y*vb0.y + a0.z*vb0.z + a0.w*vb0.w
                 + a1.x*vb1.x + a1.y*vb1.y + a1.z*vb1.z + a1.w*vb1.w;
        }
        #pragma unroll
        for (int j = 0; j < 4; j++) s[j] = warp_sum(s[j]);
        if (lane == 0) {
            #pragma unroll
            for (int j = 0; j < 4; j++)
                sout[r + j] = s[j] + (sadd ? sadd[r + j] : 0.f);
        }
    }
}

__global__ __launch_bounds__(256)
void precompute(const float* __restrict__ W1, const float* __restrict__ b1,
                const float* __restrict__ W2, const float* __restrict__ b2,
                const float* __restrict__ Wl1, const float* __restrict__ bl1,
                const float* __restrict__ Wl2, const float* __restrict__ bl2,
                const float* __restrict__ Wl3, const float* __restrict__ bl3,
                const float* __restrict__ wl4, const float* __restrict__ bl4)
{
    __shared__ __align__(16) float swl[256];
    __shared__ __align__(16) float sp1[256];
    __shared__ __align__(16) float sq[256];
    __shared__ __align__(16) float sM[256];
    __shared__ __align__(16) float sV[512];
    __shared__ float sRed[8];
    int tid = threadIdx.x, wid = tid >> 5, lane = tid & 31;

    // prefetch later-stage weights into L2, overlapping stage-0 cold reads
    #pragma unroll
    for (int j = 0; j < 8; j++) l2_prefetch(Wl2 + (size_t)(tid + 256 * j) * 32);
    #pragma unroll
    for (int j = 0; j < 8; j++) l2_prefetch(Wl1 + (size_t)(tid + 256 * j) * 32);
    l2_prefetch(W2 + (size_t)tid * 32);
    if (tid < 56) l2_prefetch(W1 + (size_t)tid * 32);

    swl[tid] = wl4[tid];
    __syncthreads();

    mv_stage(Wl3, swl, nullptr, sp1, wid, lane);   // p1 = Wl3.wl4
    __syncthreads();
    mv_stage(Wl2, sp1, swl, sq, wid, lane);        // q = Wl2.p1 + wl4
    __syncthreads();
    mv_stage(Wl1, sq, swl, sM, wid, lane);         // M = Wl1.q + wl4
    __syncthreads();

    // ---- finalize
    float contrib = bl1[tid] * sq[tid] + bl2[tid] * sp1[tid] + bl3[tid] * swl[tid];
    if (tid < 64)
        contrib += b2[tid] * (sM[tid] + sM[64 + tid] + sM[128 + tid] + sM[192 + tid]);
    contrib = warp_sum(contrib);
    if (lane == 0) sRed[wid] = contrib;

    // V[n*128+k] = W2[k,:] . M_n   (2 outputs/thread)
    #pragma unroll
    for (int rep = 0; rep < 2; rep++) {
        int o = tid + rep * 256;
        int n = o >> 7, k = o & 127;
        const float4* w4 = (const float4*)(W2 + (size_t)k * 64);
        const float4* m4 = (const float4*)(sM + n * 64);
        float a = 0.f;
        #pragma unroll
        for (int j = 0; j < 16; j++) {
            float4 w = w4[j], mm = m4[j];
            a += w.x * mm.x + w.y * mm.y + w.z * mm.z + w.w * mm.w;
        }
        sV[o] = a;
    }
    __syncthreads();

    // T/s/c1: warp wid handles rows wid*8 .. wid*8+7
    #pragma unroll
    for (int j = 0; j < 8; j++) {
        int rr = wid * 8 + j;
        if (rr < 60) {
            int nn = (rr < 56) ? (rr / 14) : (rr - 56);
            float4 w = (rr < 56)
                ? ((const float4*)(W1 + (size_t)(rr % 14) * 128))[lane]
                : ((const float4*)b1)[lane];
            float4 vv = ((const float4*)(sV + nn * 128))[lane];
            float a = w.x*vv.x + w.y*vv.y + w.z*vv.z + w.w*vv.w;
            a = warp_sum(a);
            if (lane == 0) g_TSC[rr] = a;
        } else if (rr == 60 && lane == 0) {
            float c = bl4[0];
            #pragma unroll
            for (int q = 0; q < 8; q++) c += sRed[q];
            g_TSC[60] = c;
        }
    }
}

// ---- main kernel: vectorized shared staging, LDS.64 compute, low regs
#define TPB 128

__global__ __launch_bounds__(TPB, 5)
void gcn_main(const float* __restrict__ x, const int* __restrict__ eidx,
              float* __restrict__ out)
{
    __shared__ float4 sx4[TPB * 15];   // 60 floats/sample (pad 56->60)
    __shared__ int4   se4[TPB * 7];    // 28 ints/sample  (pad 24->28)
    __shared__ float  sT[64];
    int tid = threadIdx.x;

    const float4* Xg = (const float4*)x + (size_t)blockIdx.x * TPB * 14;
    const int4*   Eg = (const int4*)eidx + (size_t)blockIdx.x * TPB * 6;
    if (tid < 61) sT[tid] = g_TSC[tid];

    // stage x in two chunks of 7 (lower peak registers, MLP=7 each)
    #pragma unroll
    for (int h = 0; h < 2; h++) {
        float4 xa[7];
        #pragma unroll
        for (int i = 0; i < 7; i++) xa[i] = Xg[(h * 7 + i) * TPB + tid];
        #pragma unroll
        for (int i = 0; i < 7; i++) {
            int idx4 = (h * 7 + i) * TPB + tid;
            int s = idx4 / 14, j = idx4 % 14;
            sx4[s * 15 + j] = xa[i];
        }
    }
    {
        int4 ev[6];
        #pragma unroll
        for (int i = 0; i < 6; i++) ev[i] = Eg[i * TPB + tid];
        #pragma unroll
        for (int i = 0; i < 6; i++) {
            int i4 = i * TPB + tid;
            int s = i4 / 6, r = i4 % 6;
            se4[s * 7 + r] = ev[i];
        }
    }
    __syncthreads();

    // ---- per-sample graph math
    const int4* me4 = se4 + tid * 7;
    int4 f0 = me4[0], f1 = me4[1], f2 = me4[2];
    int4 f3 = me4[3], f4 = me4[4], f5 = me4[5];
    int es[12] = {f0.x,f0.y,f0.z,f0.w, f1.x,f1.y,f1.z,f1.w, f2.x,f2.y,f2.z,f2.w};
    int ed[12] = {f3.x,f3.y,f3.z,f3.w, f4.x,f4.y,f4.z,f4.w, f5.x,f5.y,f5.z,f5.w};
    unsigned h0 = 1u + (1u << 20);         // self loops: codes 0, 5
    unsigned h1 = (1u << 8) + (1u << 28);  // codes 10, 15
    #pragma unroll
    for (int e = 0; e < 12; e++) {
        int code = (ed[e] << 2) | es[e];
        unsigned inc = 1u << ((code & 7) << 2);
        if (code & 8) h1 += inc; else h0 += inc;
    }
    float c[16];
    #pragma unroll
    for (int qd = 0; qd < 8; qd++) {
        c[qd]     = (float)((h0 >> (qd * 4)) & 15u);
        c[qd + 8] = (float)((h1 >> (qd * 4)) & 15u);
    }
    float dinv[4];
    #pragma unroll
    for (int dd = 0; dd < 4; dd++)
        dinv[dd] = rsqrtf(c[4*dd] + c[4*dd+1] + c[4*dd+2] + c[4*dd+3]);
    float A[16];
    #pragma unroll
    for (int dd = 0; dd < 4; dd++)
        #pragma unroll
        for (int ss = 0; ss < 4; ss++)
            A[dd*4+ss] = c[dd*4+ss] * dinv[dd] * dinv[ss];
    float A2[16], R[4];
    #pragma unroll
    for (int n = 0; n < 4; n++) {
        R[n] = A[n*4] + A[n*4+1] + A[n*4+2] + A[n*4+3];
        #pragma unroll
        for (int p = 0; p < 4; p++) {
            A2[n*4+p] = A[n*4+0] * A[0*4+p] + A[n*4+1] * A[1*4+p]
                      + A[n*4+2] * A[2*4+p] + A[n*4+3] * A[3*4+p];
        }
    }

    // ---- d2[p*4+n] = x_p . t_n, packed f32x2 FMA, x pairs straight from smem
    const float* mxf = (const float*)(sx4 + tid * 15);
    unsigned long long d2[16];
    #pragma unroll
    for (int i = 0; i < 16; i++) d2[i] = 0ULL;
    #pragma unroll
    for (int q = 0; q < 7; q++) {
        unsigned long long xp[4], tp[4];
        #pragma unroll
        for (int p = 0; p < 4; p++)
            xp[p] = *(const unsigned long long*)(mxf + p * 14 + 2 * q);  // LDS.64
        #pragma unroll
        for (int n = 0; n < 4; n++)
            tp[n] = *(const unsigned long long*)(sT + n * 14 + 2 * q);
        #pragma unroll
        for (int p = 0; p < 4; p++)
            #pragma unroll
            for (int n = 0; n < 4; n++)
                fma2(d2[p*4+n], xp[p], tp[n]);
    }

    float acc = sT[60] + R[0]*sT[56] + R[1]*sT[57] + R[2]*sT[58] + R[3]*sT[59];
    #pragma unroll
    for (int n = 0; n < 4; n++)
        #pragma unroll
        for (int p = 0; p < 4; p++)
            acc += A2[n*4+p] * unpack_sum(d2[p*4+n]);

    out[blockIdx.x * TPB + tid] = acc;
}

extern "C" void kernel_launch(void* const* d_in, const int* in_sizes, int n_in,
                              void* d_out, int out_size)
{
    const float* x   = (const float*)d_in[0];
    const int*   ei  = (const int*)  d_in[1];
    const float* W1  = (const float*)d_in[2];
    const float* b1  = (const float*)d_in[3];
    const float* W2  = (const float*)d_in[4];
    const float* b2  = (const float*)d_in[5];
    const float* Wl1 = (const float*)d_in[6];
    const float* bl1 = (const float*)d_in[7];
    const float* Wl2 = (const float*)d_in[8];
    const float* bl2 = (const float*)d_in[9];
    const float* Wl3 = (const float*)d_in[10];
    const float* bl3 = (const float*)d_in[11];
    const float* wl4 = (const float*)d_in[12];
    const float* bl4 = (const float*)d_in[13];

    int B = in_sizes[0] / 56;   // 262144

    precompute<<<1, 256>>>(W1, b1, W2, b2, Wl1, bl1, Wl2, bl2, Wl3, bl3, wl4, bl4);
    gcn_main<<<B / TPB, TPB>>>(x, ei, (float*)d_out);
}